// round 10
// baseline (speedup 1.0000x reference)
#include <cuda_runtime.h>
#include <cuda_fp16.h>
#include <mma.h>
#include <cstdint>

using namespace nvcuda;

// ============================================================================
// Problem dims (fixed by setup_inputs)
// ============================================================================
#define B_SZ    2
#define S_LEN   2048
#define D_DIM   2048
#define H_DIM   2048
#define F_DIM   6144
#define KCONV   4
#define TOKENS  (B_SZ * S_LEN)   // 4096

#define TD ((size_t)TOKENS * D_DIM)      // 8,388,608
#define TF ((size_t)TOKENS * F_DIM)      // 25,165,824
#define WH_HALVES ((size_t)5 * D_DIM * H_DIM + 3 * (size_t)D_DIM * F_DIM)
#define NCH 32
#define CHL (S_LEN / NCH)                 // 64
#define BNH ((size_t)B_SZ * NCH * H_DIM)  // 131072
// fp32: Asum/Bsum/init (3*BNH)
// fp16: 9 TD-sized buffers + f1gh (TF) + weights
#define SCRATCH_FLOATS (3 * BNH + (9 * TD + TF + WH_HALVES + 1) / 2 + 64)
__device__ float g_scratch[SCRATCH_FLOATS];

// ============================================================================
// common helpers
// ============================================================================
__device__ __forceinline__ void cp_async16(uint32_t sdst, const void* gsrc) {
    asm volatile("cp.async.cg.shared.global [%0], [%1], 16;"
                 :: "r"(sdst), "l"(gsrc) : "memory");
}
__device__ __forceinline__ void cp_commit() {
    asm volatile("cp.async.commit_group;" ::: "memory");
}
template <int N>
__device__ __forceinline__ void cp_wait() {
    asm volatile("cp.async.wait_group %0;" :: "n"(N) : "memory");
}
__device__ __forceinline__ float gelu_f(float x) {
    return 0.5f * x * (1.0f + erff(x * 0.70710678118654752440f));
}
__device__ __forceinline__ float sigmoid_f(float x) {
    return 1.0f / (1.0f + expf(-x));
}

// ============================================================================
// Single-output fp16 GEMM (dual-B scatter by Nsplit), fused epilogue.
// Tile 128x128x64, 256 threads, 3-stage cp.async. 2 CTAs/SM.
// OUTH: fp16 output; RESH: residual source is fp16 (else fp32).
// ============================================================================
#define BM 128
#define BN 128
#define BK 64
#define STAGES 3
#define LDA_S 72
#define LDB_S 136
#define LDC_S 132
#define A_ST (BM * LDA_S)                     // 9216 halves
#define B_ST (BK * LDB_S)                     // 8704 halves
#define STAGE_HALVES (A_ST + B_ST)            // 17920
#define PIPE_BYTES (STAGES * STAGE_HALVES * 2)   // 107,520
#define EPI_BYTES (BM * LDC_S * 4)               // 67,584
#define GEMM_SMEM (PIPE_BYTES > EPI_BYTES ? PIPE_BYTES : EPI_BYTES)

// ACT: 0 none, 1 gelu
template <int ACT0, int ACT1, bool RES, bool OUTH, bool RESH>
__global__ void __launch_bounds__(256, 2)
gemm_h_kernel(const __half* __restrict__ A,
              const __half* __restrict__ B0, const __half* __restrict__ B1,
              void* __restrict__ C0, int ldc0, const float* __restrict__ bias0,
              void* __restrict__ C1, int ldc1, const float* __restrict__ bias1,
              const void* __restrict__ res,
              int M, int K, int Nsplit, int ldb0, int ldb1) {
    extern __shared__ __half smemh[];
    const int tid = threadIdx.x;
    const int warp = tid >> 5;
    const int bm = blockIdx.y * BM;
    const int bn = blockIdx.x * BN;

    const bool half1 = (bn >= Nsplit);
    const __half* Bsel = half1 ? B1 : B0;
    const int ldb = half1 ? ldb1 : ldb0;
    const int cb = bn - (half1 ? Nsplit : 0);

    const int wm = (warp >> 1) * 32;
    const int wn = (warp & 1) * 64;

    wmma::fragment<wmma::accumulator, 16, 16, 16, float> acc[2][4];
    #pragma unroll
    for (int mi = 0; mi < 2; mi++)
        #pragma unroll
        for (int ni = 0; ni < 4; ni++)
            wmma::fill_fragment(acc[mi][ni], 0.0f);

    const uint32_t smem_u32 = (uint32_t)__cvta_generic_to_shared(smemh);
    const int nk = K / BK;
    const __half* Abase = A + (size_t)bm * K;
    const __half* Bbase = Bsel + cb;

    auto issue_stage = [&](int s, int kc) {
        const uint32_t sA = smem_u32 + (uint32_t)(s * STAGE_HALVES) * 2u;
        const uint32_t sB = sA + (uint32_t)A_ST * 2u;
        const __half* Ab = Abase + (size_t)kc * BK;
        const __half* Bb = Bbase + (size_t)kc * BK * ldb;
        #pragma unroll
        for (int p = 0; p < 4; p++) {       // A: 128 rows x 8 chunks(8h)
            int id = p * 256 + tid;
            int r = id >> 3, c = id & 7;
            cp_async16(sA + (uint32_t)(r * LDA_S + c * 8) * 2u,
                       Ab + (size_t)r * K + c * 8);
        }
        #pragma unroll
        for (int p = 0; p < 4; p++) {       // B: 64 rows x 16 chunks
            int id = p * 256 + tid;
            int r = id >> 4, c = id & 15;
            cp_async16(sB + (uint32_t)(r * LDB_S + c * 8) * 2u,
                       Bb + (size_t)r * ldb + c * 8);
        }
    };

    #pragma unroll
    for (int s = 0; s < STAGES - 1; s++) { issue_stage(s, s); cp_commit(); }

    int cur = 0;
    for (int kc = 0; kc < nk; kc++) {
        cp_wait<STAGES - 2>();
        __syncthreads();
        int pf = kc + STAGES - 1;
        if (pf < nk) {
            int s = cur + STAGES - 1;
            if (s >= STAGES) s -= STAGES;
            issue_stage(s, pf);
        }
        cp_commit();

        const __half* sA = smemh + cur * STAGE_HALVES;
        const __half* sB = sA + A_ST;
        #pragma unroll
        for (int kk = 0; kk < BK; kk += 16) {
            wmma::fragment<wmma::matrix_b, 16, 16, 16, __half,
                           wmma::row_major> bf[4];
            #pragma unroll
            for (int ni = 0; ni < 4; ni++)
                wmma::load_matrix_sync(bf[ni], sB + kk * LDB_S + wn + ni * 16,
                                       LDB_S);
            #pragma unroll
            for (int mi = 0; mi < 2; mi++) {
                wmma::fragment<wmma::matrix_a, 16, 16, 16, __half,
                               wmma::row_major> af;
                wmma::load_matrix_sync(af, sA + (wm + mi * 16) * LDA_S + kk,
                                       LDA_S);
                #pragma unroll
                for (int ni = 0; ni < 4; ni++)
                    wmma::mma_sync(acc[mi][ni], af, bf[ni], acc[mi][ni]);
            }
        }
        cur = (cur + 1 == STAGES) ? 0 : cur + 1;
    }

    cp_wait<0>();
    __syncthreads();
    float* Cs = reinterpret_cast<float*>(smemh);
    #pragma unroll
    for (int mi = 0; mi < 2; mi++)
        #pragma unroll
        for (int ni = 0; ni < 4; ni++)
            wmma::store_matrix_sync(Cs + (wm + mi * 16) * LDC_S + wn + ni * 16,
                                    acc[mi][ni], LDC_S, wmma::mem_row_major);
    __syncthreads();

    void* Cout = half1 ? C1 : C0;
    const int ldc = half1 ? ldc1 : ldc0;
    const float* bias = half1 ? bias1 : bias0;
    const int act = half1 ? ACT1 : ACT0;

    const int r = tid >> 1;
    const int cseg = (tid & 1) * 64;
    const size_t grow = (size_t)(bm + r);
    const float* biasp = bias + cb + cseg;
    const float* csrow = Cs + r * LDC_S + cseg;

    #pragma unroll
    for (int j = 0; j < 16; j++) {
        float4 v = *(const float4*)(csrow + j * 4);
        float4 b = *(const float4*)(biasp + j * 4);
        v.x += b.x; v.y += b.y; v.z += b.z; v.w += b.w;
        if (act == 1) {
            v.x = gelu_f(v.x); v.y = gelu_f(v.y);
            v.z = gelu_f(v.z); v.w = gelu_f(v.w);
        }
        if (RES) {
            if (RESH) {
                const __half2* rp2 = (const __half2*)(
                    (const __half*)res + grow * ldc0 + cb + cseg + j * 4);
                float2 r01 = __half22float2(rp2[0]);
                float2 r23 = __half22float2(rp2[1]);
                v.x += r01.x; v.y += r01.y; v.z += r23.x; v.w += r23.y;
            } else {
                float4 rv = *(const float4*)(
                    (const float*)res + grow * ldc0 + cb + cseg + j * 4);
                v.x += rv.x; v.y += rv.y; v.z += rv.z; v.w += rv.w;
            }
        }
        if (OUTH) {
            __half* gout = (__half*)Cout + grow * ldc + cb + cseg;
            __half2* dst = (__half2*)(gout + j * 4);
            dst[0] = __floats2half2_rn(v.x, v.y);
            dst[1] = __floats2half2_rn(v.z, v.w);
        } else {
            float* gout = (float*)Cout + grow * ldc + cb + cseg;
            *(float4*)(gout + j * 4) = v;
        }
    }
}

// ============================================================================
// Dual-accumulator GEMM (same N cols of A@B0 and A@B1, combined epilogue).
// Tile 128 x 64(x2) x 64, 256 threads, 3-stage cp.async. All outputs fp16.
// COMBINE 0 (GLU): out0h = half( gelu(v0+b0) * (v1+b1) )
// COMBINE 1 (AB):  out0h = a = exp(-8*softplus(ap)*sig(v0+b0));
//                  out1h = b = sqrt(-expm1(2la))*sig(v1+b1)*xc  (xc fp16)
// ============================================================================
#define BND 64
#define LDBD 72
#define B_STD (BK * LDBD)                       // 4608 halves
#define STAGE_D (A_ST + 2 * B_STD)              // 18432 halves
#define PIPE_D_BYTES (STAGES * STAGE_D * 2)     // 110,592
#define LDC_D 68
#define EPI_D_BYTES (2 * BM * LDC_D * 4)        // 69,632
#define GEMM_D_SMEM (PIPE_D_BYTES > EPI_D_BYTES ? PIPE_D_BYTES : EPI_D_BYTES)

template <int COMBINE>
__global__ void __launch_bounds__(256, 2)
gemm_dual_kernel(const __half* __restrict__ A,
                 const __half* __restrict__ B0, const __half* __restrict__ B1,
                 __half* __restrict__ out0h, __half* __restrict__ out1h,
                 const float* __restrict__ bias0,
                 const float* __restrict__ bias1,
                 const __half* __restrict__ xch, const float* __restrict__ ap,
                 int M, int N, int K, int ldb) {
    extern __shared__ __half smemh[];
    const int tid = threadIdx.x;
    const int warp = tid >> 5;
    const int bm = blockIdx.y * BM;
    const int bn = blockIdx.x * BND;

    const int wm = (warp >> 1) * 32;
    const int wn = (warp & 1) * 32;

    wmma::fragment<wmma::accumulator, 16, 16, 16, float> acc0[2][2], acc1[2][2];
    #pragma unroll
    for (int mi = 0; mi < 2; mi++)
        #pragma unroll
        for (int ni = 0; ni < 2; ni++) {
            wmma::fill_fragment(acc0[mi][ni], 0.0f);
            wmma::fill_fragment(acc1[mi][ni], 0.0f);
        }

    const uint32_t smem_u32 = (uint32_t)__cvta_generic_to_shared(smemh);
    const int nk = K / BK;
    const __half* Abase = A + (size_t)bm * K;
    const __half* B0base = B0 + bn;
    const __half* B1base = B1 + bn;

    auto issue_stage = [&](int s, int kc) {
        const uint32_t sA = smem_u32 + (uint32_t)(s * STAGE_D) * 2u;
        const uint32_t sB0 = sA + (uint32_t)A_ST * 2u;
        const uint32_t sB1 = sB0 + (uint32_t)B_STD * 2u;
        const __half* Ab = Abase + (size_t)kc * BK;
        const size_t brow = (size_t)kc * BK * ldb;
        #pragma unroll
        for (int p = 0; p < 4; p++) {       // A: 128 rows x 8 chunks
            int id = p * 256 + tid;
            int r = id >> 3, c = id & 7;
            cp_async16(sA + (uint32_t)(r * LDA_S + c * 8) * 2u,
                       Ab + (size_t)r * K + c * 8);
        }
        #pragma unroll
        for (int p = 0; p < 2; p++) {       // B0,B1: 64 rows x 8 chunks each
            int id = p * 256 + tid;
            int r = id >> 3, c = id & 7;
            cp_async16(sB0 + (uint32_t)(r * LDBD + c * 8) * 2u,
                       B0base + brow + (size_t)r * ldb + c * 8);
            cp_async16(sB1 + (uint32_t)(r * LDBD + c * 8) * 2u,
                       B1base + brow + (size_t)r * ldb + c * 8);
        }
    };

    #pragma unroll
    for (int s = 0; s < STAGES - 1; s++) { issue_stage(s, s); cp_commit(); }

    int cur = 0;
    for (int kc = 0; kc < nk; kc++) {
        cp_wait<STAGES - 2>();
        __syncthreads();
        int pf = kc + STAGES - 1;
        if (pf < nk) {
            int s = cur + STAGES - 1;
            if (s >= STAGES) s -= STAGES;
            issue_stage(s, pf);
        }
        cp_commit();

        const __half* sA = smemh + cur * STAGE_D;
        const __half* sB0 = sA + A_ST;
        const __half* sB1 = sB0 + B_STD;
        #pragma unroll
        for (int kk = 0; kk < BK; kk += 16) {
            wmma::fragment<wmma::matrix_b, 16, 16, 16, __half,
                           wmma::row_major> b0f[2], b1f[2];
            #pragma unroll
            for (int ni = 0; ni < 2; ni++) {
                wmma::load_matrix_sync(b0f[ni], sB0 + kk * LDBD + wn + ni * 16,
                                       LDBD);
                wmma::load_matrix_sync(b1f[ni], sB1 + kk * LDBD + wn + ni * 16,
                                       LDBD);
            }
            #pragma unroll
            for (int mi = 0; mi < 2; mi++) {
                wmma::fragment<wmma::matrix_a, 16, 16, 16, __half,
                               wmma::row_major> af;
                wmma::load_matrix_sync(af, sA + (wm + mi * 16) * LDA_S + kk,
                                       LDA_S);
                #pragma unroll
                for (int ni = 0; ni < 2; ni++) {
                    wmma::mma_sync(acc0[mi][ni], af, b0f[ni], acc0[mi][ni]);
                    wmma::mma_sync(acc1[mi][ni], af, b1f[ni], acc1[mi][ni]);
                }
            }
        }
        cur = (cur + 1 == STAGES) ? 0 : cur + 1;
    }

    cp_wait<0>();
    __syncthreads();
    float* Cs0 = reinterpret_cast<float*>(smemh);
    float* Cs1 = Cs0 + BM * LDC_D;
    #pragma unroll
    for (int mi = 0; mi < 2; mi++)
        #pragma unroll
        for (int ni = 0; ni < 2; ni++) {
            wmma::store_matrix_sync(Cs0 + (wm + mi * 16) * LDC_D + wn + ni * 16,
                                    acc0[mi][ni], LDC_D, wmma::mem_row_major);
            wmma::store_matrix_sync(Cs1 + (wm + mi * 16) * LDC_D + wn + ni * 16,
                                    acc1[mi][ni], LDC_D, wmma::mem_row_major);
        }
    __syncthreads();

    const int r = tid >> 1;
    const int c0 = (tid & 1) * 32;
    const size_t row = (size_t)(bm + r);
    const int gcol = bn + c0;

    #pragma unroll
    for (int j = 0; j < 8; j++) {
        const int cc = c0 + j * 4;
        float4 v0 = *(const float4*)(Cs0 + r * LDC_D + cc);
        float4 v1 = *(const float4*)(Cs1 + r * LDC_D + cc);
        float4 b0 = *(const float4*)(bias0 + gcol + j * 4);
        float4 b1 = *(const float4*)(bias1 + gcol + j * 4);
        v0.x += b0.x; v0.y += b0.y; v0.z += b0.z; v0.w += b0.w;
        v1.x += b1.x; v1.y += b1.y; v1.z += b1.z; v1.w += b1.w;
        if (COMBINE == 0) {
            float4 p;
            p.x = gelu_f(v0.x) * v1.x;
            p.y = gelu_f(v0.y) * v1.y;
            p.z = gelu_f(v0.z) * v1.z;
            p.w = gelu_f(v0.w) * v1.w;
            __half2* dst = (__half2*)(out0h + row * N + gcol + j * 4);
            dst[0] = __floats2half2_rn(p.x, p.y);
            dst[1] = __floats2half2_rn(p.z, p.w);
        } else {
            float4 apv = *(const float4*)(ap + gcol + j * 4);
            const __half2* xcp = (const __half2*)(xch + row * N + gcol + j * 4);
            float2 xc01 = __half22float2(xcp[0]);
            float2 xc23 = __half22float2(xcp[1]);
            float av[4], bv[4];
            const float xcv[4] = { xc01.x, xc01.y, xc23.x, xc23.y };
            const float r4[4] = { v0.x, v0.y, v0.z, v0.w };
            const float i4[4] = { v1.x, v1.y, v1.z, v1.w };
            const float ap4[4] = { apv.x, apv.y, apv.z, apv.w };
            #pragma unroll
            for (int q = 0; q < 4; q++) {
                float rr = sigmoid_f(r4[q]), ii = sigmoid_f(i4[q]);
                float la = -8.0f * log1pf(expf(ap4[q])) * rr;
                av[q] = expf(la);
                bv[q] = sqrtf(-expm1f(2.0f * la)) * ii * xcv[q];
            }
            __half2* da = (__half2*)(out0h + row * N + gcol + j * 4);
            da[0] = __floats2half2_rn(av[0], av[1]);
            da[1] = __floats2half2_rn(av[2], av[3]);
            __half2* db = (__half2*)(out1h + row * N + gcol + j * 4);
            db[0] = __floats2half2_rn(bv[0], bv[1]);
            db[1] = __floats2half2_rn(bv[2], bv[3]);
        }
    }
}

// ============================================================================
// Fused fp32->fp16 weight conversion: one launch, 8 segments, vectorized.
// ============================================================================
struct F2HSeg { const float* src; __half* dst; size_t n4; };
struct F2HArgs { F2HSeg seg[8]; };

__global__ void f2h_all_kernel(F2HArgs args) {
    for (int s = 0; s < 8; s++) {
        const float4* src = (const float4*)args.seg[s].src;
        __half2* dst = (__half2*)args.seg[s].dst;
        size_t n4 = args.seg[s].n4;
        for (size_t i = (size_t)blockIdx.x * blockDim.x + threadIdx.x; i < n4;
             i += (size_t)gridDim.x * blockDim.x) {
            float4 v = src[i];
            dst[i * 2 + 0] = __floats2half2_rn(v.x, v.y);
            dst[i * 2 + 1] = __floats2half2_rn(v.z, v.w);
        }
    }
}

// ============================================================================
// RMSNorm: fp32 in, fp16 out (row = 2048, 256 threads x 8 elems).
// ============================================================================
__global__ void rmsnorm_h_kernel(const float* __restrict__ x,
                                 const float* __restrict__ w,
                                 __half* __restrict__ out) {
    const int D = D_DIM;
    const float* row = x + (size_t)blockIdx.x * D;
    __half* orow = out + (size_t)blockIdx.x * D;
    const int tid = threadIdx.x;

    float4 v0 = *(const float4*)(row + tid * 8);
    float4 v1 = *(const float4*)(row + tid * 8 + 4);
    float s = v0.x * v0.x + v0.y * v0.y + v0.z * v0.z + v0.w * v0.w
            + v1.x * v1.x + v1.y * v1.y + v1.z * v1.z + v1.w * v1.w;
    #pragma unroll
    for (int off = 16; off > 0; off >>= 1)
        s += __shfl_xor_sync(0xFFFFFFFF, s, off);
    __shared__ float red[8];
    int lane = tid & 31, warp = tid >> 5;
    if (lane == 0) red[warp] = s;
    __syncthreads();
    if (warp == 0) {
        float t = (lane < 8) ? red[lane] : 0.0f;
        #pragma unroll
        for (int off = 4; off > 0; off >>= 1)
            t += __shfl_xor_sync(0xFFFFFFFF, t, off);
        if (lane == 0) red[0] = t;
    }
    __syncthreads();
    float inv = rsqrtf(red[0] / (float)D + 1e-8f);

    float4 w0 = *(const float4*)(w + tid * 8);
    float4 w1 = *(const float4*)(w + tid * 8 + 4);
    __half2* o = (__half2*)(orow + tid * 8);
    o[0] = __floats2half2_rn(w0.x * v0.x * inv, w0.y * v0.y * inv);
    o[1] = __floats2half2_rn(w0.z * v0.z * inv, w0.w * v0.w * inv);
    o[2] = __floats2half2_rn(w1.x * v1.x * inv, w1.y * v1.y * inv);
    o[3] = __floats2half2_rn(w1.z * v1.z * inv, w1.w * v1.w * inv);
}

// RMSNorm: fp16 in, fp16 out (fp32 math).
__global__ void rmsnorm_hh_kernel(const __half* __restrict__ x,
                                  const float* __restrict__ w,
                                  __half* __restrict__ out) {
    const int D = D_DIM;
    const __half2* row2 = (const __half2*)(x + (size_t)blockIdx.x * D);
    __half* orow = out + (size_t)blockIdx.x * D;
    const int tid = threadIdx.x;

    float2 xv[4];
    #pragma unroll
    for (int q = 0; q < 4; q++)
        xv[q] = __half22float2(row2[tid * 4 + q]);
    float s = 0.0f;
    #pragma unroll
    for (int q = 0; q < 4; q++)
        s += xv[q].x * xv[q].x + xv[q].y * xv[q].y;
    #pragma unroll
    for (int off = 16; off > 0; off >>= 1)
        s += __shfl_xor_sync(0xFFFFFFFF, s, off);
    __shared__ float red[8];
    int lane = tid & 31, warp = tid >> 5;
    if (lane == 0) red[warp] = s;
    __syncthreads();
    if (warp == 0) {
        float t = (lane < 8) ? red[lane] : 0.0f;
        #pragma unroll
        for (int off = 4; off > 0; off >>= 1)
            t += __shfl_xor_sync(0xFFFFFFFF, t, off);
        if (lane == 0) red[0] = t;
    }
    __syncthreads();
    float inv = rsqrtf(red[0] / (float)D + 1e-8f);

    float4 w0 = *(const float4*)(w + tid * 8);
    float4 w1 = *(const float4*)(w + tid * 8 + 4);
    __half2* o = (__half2*)(orow + tid * 8);
    o[0] = __floats2half2_rn(w0.x * xv[0].x * inv, w0.y * xv[0].y * inv);
    o[1] = __floats2half2_rn(w0.z * xv[1].x * inv, w0.w * xv[1].y * inv);
    o[2] = __floats2half2_rn(w1.x * xv[2].x * inv, w1.y * xv[2].y * inv);
    o[3] = __floats2half2_rn(w1.z * xv[3].x * inv, w1.w * xv[3].y * inv);
}

// ============================================================================
// Causal depthwise conv (K=4): fp16 in/out, 2 tokens x 8 channels per thread.
// 5 row-loads produce 2 outputs (vs 8 for 1-token threads).
// ============================================================================
__global__ void conv_h_kernel(const __half* __restrict__ xh,
                              const float* __restrict__ w,
                              const float* __restrict__ bias,
                              __half* __restrict__ yh) {
    const int i = blockIdx.x * blockDim.x + threadIdx.x;  // TOKENS*H/16 thr
    const int h8 = (i & (H_DIM / 8 - 1)) * 8;
    const int tp = i >> 8;            // token-pair index
    const int tok0 = tp * 2;
    const int t = tok0 & (S_LEN - 1); // even; pair never crosses batch
    const int bb = tok0 >> 11;

    // preload weights (4 taps x 8 channels)
    float wv[4][8];
    #pragma unroll
    for (int k = 0; k < KCONV; k++) {
        float4 a = *(const float4*)(w + k * H_DIM + h8);
        float4 b = *(const float4*)(w + k * H_DIM + h8 + 4);
        wv[k][0] = a.x; wv[k][1] = a.y; wv[k][2] = a.z; wv[k][3] = a.w;
        wv[k][4] = b.x; wv[k][5] = b.y; wv[k][6] = b.z; wv[k][7] = b.w;
    }
    float acc0[8], acc1[8];
    {
        float4 b0 = *(const float4*)(bias + h8);
        float4 b1 = *(const float4*)(bias + h8 + 4);
        acc0[0] = b0.x; acc0[1] = b0.y; acc0[2] = b0.z; acc0[3] = b0.w;
        acc0[4] = b1.x; acc0[5] = b1.y; acc0[6] = b1.z; acc0[7] = b1.w;
        #pragma unroll
        for (int q = 0; q < 8; q++) acc1[q] = acc0[q];
    }

    #pragma unroll
    for (int rr = -3; rr <= 1; rr++) {
        int tt = t + rr;
        if (tt < 0) continue;
        const __half2* xr = (const __half2*)(
            xh + ((size_t)(bb * S_LEN + tt)) * H_DIM + h8);
        float2 x0 = __half22float2(xr[0]);
        float2 x1 = __half22float2(xr[1]);
        float2 x2 = __half22float2(xr[2]);
        float2 x3 = __half22float2(xr[3]);
        float xv[8] = { x0.x, x0.y, x1.x, x1.y, x2.x, x2.y, x3.x, x3.y };
        int k0 = rr + 3;                // tap for output t   (rows t-3..t)
        int k1 = rr + 2;                // tap for output t+1 (rows t-2..t+1)
        if (k0 <= 3) {
            #pragma unroll
            for (int q = 0; q < 8; q++)
                acc0[q] = fmaf(wv[k0][q], xv[q], acc0[q]);
        }
        if (k1 >= 0) {
            #pragma unroll
            for (int q = 0; q < 8; q++)
                acc1[q] = fmaf(wv[k1][q], xv[q], acc1[q]);
        }
    }
    __half2* o0 = (__half2*)(yh + (size_t)(bb * S_LEN + t) * H_DIM + h8);
    o0[0] = __floats2half2_rn(acc0[0], acc0[1]);
    o0[1] = __floats2half2_rn(acc0[2], acc0[3]);
    o0[2] = __floats2half2_rn(acc0[4], acc0[5]);
    o0[3] = __floats2half2_rn(acc0[6], acc0[7]);
    __half2* o1 = (__half2*)(yh + (size_t)(bb * S_LEN + t + 1) * H_DIM + h8);
    o1[0] = __floats2half2_rn(acc1[0], acc1[1]);
    o1[1] = __floats2half2_rn(acc1[2], acc1[3]);
    o1[2] = __floats2half2_rn(acc1[4], acc1[5]);
    o1[3] = __floats2half2_rn(acc1[6], acc1[7]);
}

// ============================================================================
// Chunked RG-LRU scan, fp16 a/b/left, fp32 state. NCH=32 chunks of 64.
// ============================================================================
__global__ void scan_phaseA(const __half* __restrict__ a,
                            const __half* __restrict__ b,
                            float* __restrict__ Asum,
                            float* __restrict__ Bsum) {
    int idx2 = blockIdx.x * blockDim.x + threadIdx.x;   // BNH/2 threads
    int h2 = idx2 & (H_DIM / 2 - 1);
    int c = (idx2 >> 10) & (NCH - 1);
    int bb = idx2 >> 15;
    size_t base2 = (((size_t)(bb * S_LEN + c * CHL)) * H_DIM) / 2 + h2;
    const __half2* a2 = (const __half2*)a;
    const __half2* b2 = (const __half2*)b;
    float2 A = make_float2(1.0f, 1.0f), B = make_float2(0.0f, 0.0f);
    #pragma unroll 4
    for (int t = 0; t < CHL; t++) {
        size_t o = base2 + (size_t)t * (H_DIM / 2);
        float2 av = __half22float2(a2[o]);
        float2 bv = __half22float2(b2[o]);
        B.x = fmaf(av.x, B.x, bv.x);
        B.y = fmaf(av.y, B.y, bv.y);
        A.x *= av.x;
        A.y *= av.y;
    }
    size_t s2 = ((size_t)(bb * NCH + c) * H_DIM) / 2 + h2;
    ((float2*)Asum)[s2] = A;
    ((float2*)Bsum)[s2] = B;
}

__global__ void scan_phaseB(const float* __restrict__ Asum,
                            const float* __restrict__ Bsum,
                            float* __restrict__ init) {
    int idx = blockIdx.x * blockDim.x + threadIdx.x;    // B*H/2 threads
    int h2 = idx & (H_DIM / 2 - 1);
    int bb = idx >> 10;
    float2 state = make_float2(0.0f, 0.0f);
    #pragma unroll
    for (int c = 0; c < NCH; c++) {
        size_t s2 = ((size_t)(bb * NCH + c) * H_DIM) / 2 + h2;
        ((float2*)init)[s2] = state;
        float2 A = ((const float2*)Asum)[s2];
        float2 B = ((const float2*)Bsum)[s2];
        state.x = fmaf(A.x, state.x, B.x);
        state.y = fmaf(A.y, state.y, B.y);
    }
}

__global__ void scan_phaseC(const __half* __restrict__ a,
                            const __half* __restrict__ b,
                            const float* __restrict__ init,
                            const __half* __restrict__ left,
                            __half* __restrict__ lh) {
    int idx2 = blockIdx.x * blockDim.x + threadIdx.x;   // BNH/2 threads
    int h2 = idx2 & (H_DIM / 2 - 1);
    int c = (idx2 >> 10) & (NCH - 1);
    int bb = idx2 >> 15;
    size_t base2 = (((size_t)(bb * S_LEN + c * CHL)) * H_DIM) / 2 + h2;
    size_t s2 = ((size_t)(bb * NCH + c) * H_DIM) / 2 + h2;
    const __half2* a2 = (const __half2*)a;
    const __half2* b2 = (const __half2*)b;
    const __half2* l2 = (const __half2*)left;
    __half2* o2 = (__half2*)lh;
    float2 state = ((const float2*)init)[s2];
    #pragma unroll 4
    for (int t = 0; t < CHL; t++) {
        size_t o = base2 + (size_t)t * (H_DIM / 2);
        float2 av = __half22float2(a2[o]);
        float2 bv = __half22float2(b2[o]);
        float2 lv = __half22float2(l2[o]);
        state.x = fmaf(av.x, state.x, bv.x);
        state.y = fmaf(av.y, state.y, bv.y);
        o2[o] = __floats2half2_rn(lv.x * state.x, lv.y * state.y);
    }
}

// ============================================================================
// Host launch
// ============================================================================
template <int ACT0, int ACT1, bool RES, bool OUTH, bool RESH>
static inline void launch_gemm(const __half* A,
                               const __half* B0, const __half* B1,
                               void* C0, int ldc0, const float* bias0,
                               void* C1, int ldc1, const float* bias1,
                               const void* res,
                               int M, int Ntot, int K, int Nsplit,
                               int ldb0, int ldb1) {
    dim3 grid(Ntot / BN, M / BM);
    gemm_h_kernel<ACT0, ACT1, RES, OUTH, RESH><<<grid, 256, GEMM_SMEM>>>(
        A, B0, B1, C0, ldc0, bias0, C1, ldc1, bias1, res,
        M, K, Nsplit, ldb0, ldb1);
}

extern "C" void kernel_launch(void* const* d_in, const int* in_sizes, int n_in,
                              void* d_out, int out_size) {
    (void)in_sizes; (void)n_in; (void)out_size;
    const float* x       = (const float*)d_in[0];
    const float* norm1_w = (const float*)d_in[1];
    const float* left_W  = (const float*)d_in[2];
    const float* left_b  = (const float*)d_in[3];
    const float* right_W = (const float*)d_in[4];
    const float* right_b = (const float*)d_in[5];
    const float* conv_w  = (const float*)d_in[6];
    const float* conv_b  = (const float*)d_in[7];
    const float* ga_W    = (const float*)d_in[8];
    const float* ga_b    = (const float*)d_in[9];
    const float* gx_W    = (const float*)d_in[10];
    const float* gx_b    = (const float*)d_in[11];
    const float* a_param = (const float*)d_in[12];
    const float* out_W   = (const float*)d_in[13];
    const float* out_b   = (const float*)d_in[14];
    const float* norm2_w = (const float*)d_in[15];
    const float* up1_W   = (const float*)d_in[16];
    const float* up1_b   = (const float*)d_in[17];
    const float* up2_W   = (const float*)d_in[18];
    const float* up2_b   = (const float*)d_in[19];
    const float* down_W  = (const float*)d_in[20];
    const float* down_b  = (const float*)d_in[21];
    float* out = (float*)d_out;

    cudaFuncSetAttribute(gemm_h_kernel<1, 0, false, true, false>,
                         cudaFuncAttributeMaxDynamicSharedMemorySize, GEMM_SMEM);
    cudaFuncSetAttribute(gemm_h_kernel<0, 0, true, true, false>,
                         cudaFuncAttributeMaxDynamicSharedMemorySize, GEMM_SMEM);
    cudaFuncSetAttribute(gemm_h_kernel<0, 0, true, false, true>,
                         cudaFuncAttributeMaxDynamicSharedMemorySize, GEMM_SMEM);
    cudaFuncSetAttribute(gemm_dual_kernel<0>,
                         cudaFuncAttributeMaxDynamicSharedMemorySize, GEMM_D_SMEM);
    cudaFuncSetAttribute(gemm_dual_kernel<1>,
                         cudaFuncAttributeMaxDynamicSharedMemorySize, GEMM_D_SMEM);

    float* scratch = nullptr;
    cudaGetSymbolAddress((void**)&scratch, g_scratch);
    float* Asum = scratch;                       // [BNH]
    float* Bsum = Asum + BNH;
    float* init = Bsum + BNH;
    __half* xnh   = (__half*)(init + BNH);       // [TOKENS, D]
    __half* rph   = xnh + TD;                    // [TOKENS, H] right pre-conv
    __half* cvh   = rph + TD;                    // [TOKENS, H] conv out
    __half* lefth = cvh + TD;                    // [TOKENS, H] gelu(left)
    __half* abh   = lefth + TD;                  // [TOKENS, H] a
    __half* bbh   = abh + TD;                    // [TOKENS, H] b
    __half* lhh   = bbh + TD;                    // [TOKENS, H] left*h
    __half* x1h   = lhh + TD;                    // [TOKENS, D] residual strm
    __half* x1nh  = x1h + TD;                    // [TOKENS, D]
    __half* f1gh  = x1nh + TD;                   // [TOKENS, F]
    __half* wh    = f1gh + TF;
    __half* leftWh  = wh;
    __half* rightWh = leftWh  + (size_t)D_DIM * H_DIM;
    __half* gaWh    = rightWh + (size_t)D_DIM * H_DIM;
    __half* gxWh    = gaWh    + (size_t)H_DIM * H_DIM;
    __half* outWh   = gxWh    + (size_t)H_DIM * H_DIM;
    __half* up1Wh   = outWh   + (size_t)H_DIM * D_DIM;
    __half* up2Wh   = up1Wh   + (size_t)D_DIM * F_DIM;
    __half* downWh  = up2Wh   + (size_t)D_DIM * F_DIM;

    // ---- fused weight conversion ----
    {
        F2HArgs fa;
        fa.seg[0] = { left_W,  leftWh,  (size_t)D_DIM * H_DIM / 4 };
        fa.seg[1] = { right_W, rightWh, (size_t)D_DIM * H_DIM / 4 };
        fa.seg[2] = { ga_W,    gaWh,    (size_t)H_DIM * H_DIM / 4 };
        fa.seg[3] = { gx_W,    gxWh,    (size_t)H_DIM * H_DIM / 4 };
        fa.seg[4] = { out_W,   outWh,   (size_t)H_DIM * D_DIM / 4 };
        fa.seg[5] = { up1_W,   up1Wh,   (size_t)D_DIM * F_DIM / 4 };
        fa.seg[6] = { up2_W,   up2Wh,   (size_t)D_DIM * F_DIM / 4 };
        fa.seg[7] = { down_W,  downWh,  (size_t)F_DIM * D_DIM / 4 };
        f2h_all_kernel<<<2368, 256>>>(fa);
    }

    // ---- recurrent sub-block ----
    rmsnorm_h_kernel<<<TOKENS, 256>>>(x, norm1_w, xnh);

    launch_gemm<1, 0, false, true, false>(
        xnh, leftWh, rightWh,
        lefth, H_DIM, left_b, rph, H_DIM, right_b, nullptr,
        TOKENS, 2 * H_DIM, D_DIM, H_DIM, H_DIM, H_DIM);

    conv_h_kernel<<<TOKENS * H_DIM / 16 / 256, 256>>>(rph, conv_w, conv_b, cvh);

    {
        dim3 grid(H_DIM / BND, TOKENS / BM);
        gemm_dual_kernel<1><<<grid, 256, GEMM_D_SMEM>>>(
            cvh, gaWh, gxWh, abh, bbh, ga_b, gx_b,
            cvh, a_param, TOKENS, H_DIM, H_DIM, H_DIM);
    }

    {
        const int tA2 = (int)(BNH / 2);           // 65536
        scan_phaseA<<<tA2 / 256, 256>>>(abh, bbh, Asum, Bsum);
        scan_phaseB<<<(B_SZ * H_DIM / 2) / 256, 256>>>(Asum, Bsum, init);
        scan_phaseC<<<tA2 / 256, 256>>>(abh, bbh, init, lefth, lhh);
    }

    // out GEMM: fp16 x1 = acc + out_b + x (fp32 residual)
    launch_gemm<0, 0, true, true, false>(
        lhh, outWh, outWh,
        x1h, D_DIM, out_b, nullptr, 0, nullptr, x,
        TOKENS, D_DIM, H_DIM, D_DIM, D_DIM, D_DIM);

    // ---- gated MLP sub-block ----
    rmsnorm_hh_kernel<<<TOKENS, 256>>>(x1h, norm2_w, x1nh);

    {
        dim3 grid(F_DIM / BND, TOKENS / BM);
        gemm_dual_kernel<0><<<grid, 256, GEMM_D_SMEM>>>(
            x1nh, up1Wh, up2Wh, f1gh, nullptr, up1_b, up2_b,
            nullptr, nullptr, TOKENS, F_DIM, D_DIM, F_DIM);
    }

    // down GEMM: fp32 out = acc + down_b + x1 (fp16 residual)
    launch_gemm<0, 0, true, false, true>(
        f1gh, downWh, downWh,
        out, D_DIM, down_b, nullptr, 0, nullptr, x1h,
        TOKENS, D_DIM, F_DIM, D_DIM, D_DIM, D_DIM);
}

// round 11
// speedup vs baseline: 1.0023x; 1.0023x over previous
#include <cuda_runtime.h>
#include <cuda_fp16.h>
#include <mma.h>
#include <cstdint>

using namespace nvcuda;

// ============================================================================
// Problem dims (fixed by setup_inputs)
// ============================================================================
#define B_SZ    2
#define S_LEN   2048
#define D_DIM   2048
#define H_DIM   2048
#define F_DIM   6144
#define KCONV   4
#define TOKENS  (B_SZ * S_LEN)   // 4096

#define TD ((size_t)TOKENS * D_DIM)      // 8,388,608
#define TF ((size_t)TOKENS * F_DIM)      // 25,165,824
#define WH_HALVES ((size_t)5 * D_DIM * H_DIM + 3 * (size_t)D_DIM * F_DIM)
#define NCH 32
#define CHL (S_LEN / NCH)                 // 64
#define BNH ((size_t)B_SZ * NCH * H_DIM)  // 131072
#define SCRATCH_FLOATS (3 * BNH + (9 * TD + TF + WH_HALVES + 1) / 2 + 64)
__device__ float g_scratch[SCRATCH_FLOATS];

// ============================================================================
// common helpers
// ============================================================================
__device__ __forceinline__ void cp_async16(uint32_t sdst, const void* gsrc) {
    asm volatile("cp.async.cg.shared.global [%0], [%1], 16;"
                 :: "r"(sdst), "l"(gsrc) : "memory");
}
__device__ __forceinline__ void cp_commit() {
    asm volatile("cp.async.commit_group;" ::: "memory");
}
template <int N>
__device__ __forceinline__ void cp_wait() {
    asm volatile("cp.async.wait_group %0;" :: "n"(N) : "memory");
}
__device__ __forceinline__ float gelu_f(float x) {
    return 0.5f * x * (1.0f + erff(x * 0.70710678118654752440f));
}
__device__ __forceinline__ float sigmoid_f(float x) {
    return 1.0f / (1.0f + expf(-x));
}

// ============================================================================
// Single-output fp16 GEMM (dual-B scatter by Nsplit), fused epilogue.
// Tile 128x128x64, 256 threads, 3-stage cp.async. 2 CTAs/SM.
// OUTH: fp16 output; RESH: residual source is fp16 (else fp32).
// ============================================================================
#define BM 128
#define BN 128
#define BK 64
#define STAGES 3
#define LDA_S 72
#define LDB_S 136
#define LDC_S 132
#define A_ST (BM * LDA_S)                     // 9216 halves
#define B_ST (BK * LDB_S)                     // 8704 halves
#define STAGE_HALVES (A_ST + B_ST)            // 17920
#define PIPE_BYTES (STAGES * STAGE_HALVES * 2)   // 107,520
#define EPI_BYTES (BM * LDC_S * 4)               // 67,584
#define GEMM_SMEM (PIPE_BYTES > EPI_BYTES ? PIPE_BYTES : EPI_BYTES)

// ACT: 0 none, 1 gelu
template <int ACT0, int ACT1, bool RES, bool OUTH, bool RESH>
__global__ void __launch_bounds__(256, 2)
gemm_h_kernel(const __half* __restrict__ A,
              const __half* __restrict__ B0, const __half* __restrict__ B1,
              void* __restrict__ C0, int ldc0, const float* __restrict__ bias0,
              void* __restrict__ C1, int ldc1, const float* __restrict__ bias1,
              const void* __restrict__ res,
              int M, int K, int Nsplit, int ldb0, int ldb1) {
    extern __shared__ __half smemh[];
    const int tid = threadIdx.x;
    const int warp = tid >> 5;
    const int bm = blockIdx.y * BM;
    const int bn = blockIdx.x * BN;

    const bool half1 = (bn >= Nsplit);
    const __half* Bsel = half1 ? B1 : B0;
    const int ldb = half1 ? ldb1 : ldb0;
    const int cb = bn - (half1 ? Nsplit : 0);

    const int wm = (warp >> 1) * 32;
    const int wn = (warp & 1) * 64;

    wmma::fragment<wmma::accumulator, 16, 16, 16, float> acc[2][4];
    #pragma unroll
    for (int mi = 0; mi < 2; mi++)
        #pragma unroll
        for (int ni = 0; ni < 4; ni++)
            wmma::fill_fragment(acc[mi][ni], 0.0f);

    const uint32_t smem_u32 = (uint32_t)__cvta_generic_to_shared(smemh);
    const int nk = K / BK;
    const __half* Abase = A + (size_t)bm * K;
    const __half* Bbase = Bsel + cb;

    auto issue_stage = [&](int s, int kc) {
        const uint32_t sA = smem_u32 + (uint32_t)(s * STAGE_HALVES) * 2u;
        const uint32_t sB = sA + (uint32_t)A_ST * 2u;
        const __half* Ab = Abase + (size_t)kc * BK;
        const __half* Bb = Bbase + (size_t)kc * BK * ldb;
        #pragma unroll
        for (int p = 0; p < 4; p++) {       // A: 128 rows x 8 chunks(8h)
            int id = p * 256 + tid;
            int r = id >> 3, c = id & 7;
            cp_async16(sA + (uint32_t)(r * LDA_S + c * 8) * 2u,
                       Ab + (size_t)r * K + c * 8);
        }
        #pragma unroll
        for (int p = 0; p < 4; p++) {       // B: 64 rows x 16 chunks
            int id = p * 256 + tid;
            int r = id >> 4, c = id & 15;
            cp_async16(sB + (uint32_t)(r * LDB_S + c * 8) * 2u,
                       Bb + (size_t)r * ldb + c * 8);
        }
    };

    #pragma unroll
    for (int s = 0; s < STAGES - 1; s++) { issue_stage(s, s); cp_commit(); }

    int cur = 0;
    for (int kc = 0; kc < nk; kc++) {
        cp_wait<STAGES - 2>();
        __syncthreads();
        int pf = kc + STAGES - 1;
        if (pf < nk) {
            int s = cur + STAGES - 1;
            if (s >= STAGES) s -= STAGES;
            issue_stage(s, pf);
        }
        cp_commit();

        const __half* sA = smemh + cur * STAGE_HALVES;
        const __half* sB = sA + A_ST;
        #pragma unroll
        for (int kk = 0; kk < BK; kk += 16) {
            wmma::fragment<wmma::matrix_b, 16, 16, 16, __half,
                           wmma::row_major> bf[4];
            #pragma unroll
            for (int ni = 0; ni < 4; ni++)
                wmma::load_matrix_sync(bf[ni], sB + kk * LDB_S + wn + ni * 16,
                                       LDB_S);
            #pragma unroll
            for (int mi = 0; mi < 2; mi++) {
                wmma::fragment<wmma::matrix_a, 16, 16, 16, __half,
                               wmma::row_major> af;
                wmma::load_matrix_sync(af, sA + (wm + mi * 16) * LDA_S + kk,
                                       LDA_S);
                #pragma unroll
                for (int ni = 0; ni < 4; ni++)
                    wmma::mma_sync(acc[mi][ni], af, bf[ni], acc[mi][ni]);
            }
        }
        cur = (cur + 1 == STAGES) ? 0 : cur + 1;
    }

    cp_wait<0>();
    __syncthreads();
    float* Cs = reinterpret_cast<float*>(smemh);
    #pragma unroll
    for (int mi = 0; mi < 2; mi++)
        #pragma unroll
        for (int ni = 0; ni < 4; ni++)
            wmma::store_matrix_sync(Cs + (wm + mi * 16) * LDC_S + wn + ni * 16,
                                    acc[mi][ni], LDC_S, wmma::mem_row_major);
    __syncthreads();

    void* Cout = half1 ? C1 : C0;
    const int ldc = half1 ? ldc1 : ldc0;
    const float* bias = half1 ? bias1 : bias0;
    const int act = half1 ? ACT1 : ACT0;

    const int r = tid >> 1;
    const int cseg = (tid & 1) * 64;
    const size_t grow = (size_t)(bm + r);
    const float* biasp = bias + cb + cseg;
    const float* csrow = Cs + r * LDC_S + cseg;

    #pragma unroll
    for (int j = 0; j < 16; j++) {
        float4 v = *(const float4*)(csrow + j * 4);
        float4 b = *(const float4*)(biasp + j * 4);
        v.x += b.x; v.y += b.y; v.z += b.z; v.w += b.w;
        if (act == 1) {
            v.x = gelu_f(v.x); v.y = gelu_f(v.y);
            v.z = gelu_f(v.z); v.w = gelu_f(v.w);
        }
        if (RES) {
            if (RESH) {
                const __half2* rp2 = (const __half2*)(
                    (const __half*)res + grow * ldc0 + cb + cseg + j * 4);
                float2 r01 = __half22float2(rp2[0]);
                float2 r23 = __half22float2(rp2[1]);
                v.x += r01.x; v.y += r01.y; v.z += r23.x; v.w += r23.y;
            } else {
                float4 rv = *(const float4*)(
                    (const float*)res + grow * ldc0 + cb + cseg + j * 4);
                v.x += rv.x; v.y += rv.y; v.z += rv.z; v.w += rv.w;
            }
        }
        if (OUTH) {
            __half* gout = (__half*)Cout + grow * ldc + cb + cseg;
            __half2* dst = (__half2*)(gout + j * 4);
            dst[0] = __floats2half2_rn(v.x, v.y);
            dst[1] = __floats2half2_rn(v.z, v.w);
        } else {
            float* gout = (float*)Cout + grow * ldc + cb + cseg;
            *(float4*)(gout + j * 4) = v;
        }
    }
}

// ============================================================================
// Dual-accumulator GEMM (same N cols of A@B0 and A@B1, combined epilogue).
// Tile 128 x 64(x2) x 64, 256 threads, 3-stage cp.async. All outputs fp16.
// COMBINE 0 (GLU): out0h = half( gelu(v0+b0) * (v1+b1) )
// COMBINE 1 (AB):  out0h = a = exp(-8*softplus(ap)*sig(v0+b0));
//                  out1h = b = sqrt(-expm1(2la))*sig(v1+b1)*xc  (xc fp16)
// ============================================================================
#define BND 64
#define LDBD 72
#define B_STD (BK * LDBD)                       // 4608 halves
#define STAGE_D (A_ST + 2 * B_STD)              // 18432 halves
#define PIPE_D_BYTES (STAGES * STAGE_D * 2)     // 110,592
#define LDC_D 68
#define EPI_D_BYTES (2 * BM * LDC_D * 4)        // 69,632
#define GEMM_D_SMEM (PIPE_D_BYTES > EPI_D_BYTES ? PIPE_D_BYTES : EPI_D_BYTES)

template <int COMBINE>
__global__ void __launch_bounds__(256, 2)
gemm_dual_kernel(const __half* __restrict__ A,
                 const __half* __restrict__ B0, const __half* __restrict__ B1,
                 __half* __restrict__ out0h, __half* __restrict__ out1h,
                 const float* __restrict__ bias0,
                 const float* __restrict__ bias1,
                 const __half* __restrict__ xch, const float* __restrict__ ap,
                 int M, int N, int K, int ldb) {
    extern __shared__ __half smemh[];
    const int tid = threadIdx.x;
    const int warp = tid >> 5;
    const int bm = blockIdx.y * BM;
    const int bn = blockIdx.x * BND;

    const int wm = (warp >> 1) * 32;
    const int wn = (warp & 1) * 32;

    wmma::fragment<wmma::accumulator, 16, 16, 16, float> acc0[2][2], acc1[2][2];
    #pragma unroll
    for (int mi = 0; mi < 2; mi++)
        #pragma unroll
        for (int ni = 0; ni < 2; ni++) {
            wmma::fill_fragment(acc0[mi][ni], 0.0f);
            wmma::fill_fragment(acc1[mi][ni], 0.0f);
        }

    const uint32_t smem_u32 = (uint32_t)__cvta_generic_to_shared(smemh);
    const int nk = K / BK;
    const __half* Abase = A + (size_t)bm * K;
    const __half* B0base = B0 + bn;
    const __half* B1base = B1 + bn;

    auto issue_stage = [&](int s, int kc) {
        const uint32_t sA = smem_u32 + (uint32_t)(s * STAGE_D) * 2u;
        const uint32_t sB0 = sA + (uint32_t)A_ST * 2u;
        const uint32_t sB1 = sB0 + (uint32_t)B_STD * 2u;
        const __half* Ab = Abase + (size_t)kc * BK;
        const size_t brow = (size_t)kc * BK * ldb;
        #pragma unroll
        for (int p = 0; p < 4; p++) {       // A: 128 rows x 8 chunks
            int id = p * 256 + tid;
            int r = id >> 3, c = id & 7;
            cp_async16(sA + (uint32_t)(r * LDA_S + c * 8) * 2u,
                       Ab + (size_t)r * K + c * 8);
        }
        #pragma unroll
        for (int p = 0; p < 2; p++) {       // B0,B1: 64 rows x 8 chunks each
            int id = p * 256 + tid;
            int r = id >> 3, c = id & 7;
            cp_async16(sB0 + (uint32_t)(r * LDBD + c * 8) * 2u,
                       B0base + brow + (size_t)r * ldb + c * 8);
            cp_async16(sB1 + (uint32_t)(r * LDBD + c * 8) * 2u,
                       B1base + brow + (size_t)r * ldb + c * 8);
        }
    };

    #pragma unroll
    for (int s = 0; s < STAGES - 1; s++) { issue_stage(s, s); cp_commit(); }

    int cur = 0;
    for (int kc = 0; kc < nk; kc++) {
        cp_wait<STAGES - 2>();
        __syncthreads();
        int pf = kc + STAGES - 1;
        if (pf < nk) {
            int s = cur + STAGES - 1;
            if (s >= STAGES) s -= STAGES;
            issue_stage(s, pf);
        }
        cp_commit();

        const __half* sA = smemh + cur * STAGE_D;
        const __half* sB0 = sA + A_ST;
        const __half* sB1 = sB0 + B_STD;
        #pragma unroll
        for (int kk = 0; kk < BK; kk += 16) {
            wmma::fragment<wmma::matrix_b, 16, 16, 16, __half,
                           wmma::row_major> b0f[2], b1f[2];
            #pragma unroll
            for (int ni = 0; ni < 2; ni++) {
                wmma::load_matrix_sync(b0f[ni], sB0 + kk * LDBD + wn + ni * 16,
                                       LDBD);
                wmma::load_matrix_sync(b1f[ni], sB1 + kk * LDBD + wn + ni * 16,
                                       LDBD);
            }
            #pragma unroll
            for (int mi = 0; mi < 2; mi++) {
                wmma::fragment<wmma::matrix_a, 16, 16, 16, __half,
                               wmma::row_major> af;
                wmma::load_matrix_sync(af, sA + (wm + mi * 16) * LDA_S + kk,
                                       LDA_S);
                #pragma unroll
                for (int ni = 0; ni < 2; ni++) {
                    wmma::mma_sync(acc0[mi][ni], af, b0f[ni], acc0[mi][ni]);
                    wmma::mma_sync(acc1[mi][ni], af, b1f[ni], acc1[mi][ni]);
                }
            }
        }
        cur = (cur + 1 == STAGES) ? 0 : cur + 1;
    }

    cp_wait<0>();
    __syncthreads();
    float* Cs0 = reinterpret_cast<float*>(smemh);
    float* Cs1 = Cs0 + BM * LDC_D;
    #pragma unroll
    for (int mi = 0; mi < 2; mi++)
        #pragma unroll
        for (int ni = 0; ni < 2; ni++) {
            wmma::store_matrix_sync(Cs0 + (wm + mi * 16) * LDC_D + wn + ni * 16,
                                    acc0[mi][ni], LDC_D, wmma::mem_row_major);
            wmma::store_matrix_sync(Cs1 + (wm + mi * 16) * LDC_D + wn + ni * 16,
                                    acc1[mi][ni], LDC_D, wmma::mem_row_major);
        }
    __syncthreads();

    const int r = tid >> 1;
    const int c0 = (tid & 1) * 32;
    const size_t row = (size_t)(bm + r);
    const int gcol = bn + c0;

    #pragma unroll
    for (int j = 0; j < 8; j++) {
        const int cc = c0 + j * 4;
        float4 v0 = *(const float4*)(Cs0 + r * LDC_D + cc);
        float4 v1 = *(const float4*)(Cs1 + r * LDC_D + cc);
        float4 b0 = *(const float4*)(bias0 + gcol + j * 4);
        float4 b1 = *(const float4*)(bias1 + gcol + j * 4);
        v0.x += b0.x; v0.y += b0.y; v0.z += b0.z; v0.w += b0.w;
        v1.x += b1.x; v1.y += b1.y; v1.z += b1.z; v1.w += b1.w;
        if (COMBINE == 0) {
            float4 p;
            p.x = gelu_f(v0.x) * v1.x;
            p.y = gelu_f(v0.y) * v1.y;
            p.z = gelu_f(v0.z) * v1.z;
            p.w = gelu_f(v0.w) * v1.w;
            __half2* dst = (__half2*)(out0h + row * N + gcol + j * 4);
            dst[0] = __floats2half2_rn(p.x, p.y);
            dst[1] = __floats2half2_rn(p.z, p.w);
        } else {
            float4 apv = *(const float4*)(ap + gcol + j * 4);
            const __half2* xcp = (const __half2*)(xch + row * N + gcol + j * 4);
            float2 xc01 = __half22float2(xcp[0]);
            float2 xc23 = __half22float2(xcp[1]);
            float av[4], bv[4];
            const float xcv[4] = { xc01.x, xc01.y, xc23.x, xc23.y };
            const float r4[4] = { v0.x, v0.y, v0.z, v0.w };
            const float i4[4] = { v1.x, v1.y, v1.z, v1.w };
            const float ap4[4] = { apv.x, apv.y, apv.z, apv.w };
            #pragma unroll
            for (int q = 0; q < 4; q++) {
                float rr = sigmoid_f(r4[q]), ii = sigmoid_f(i4[q]);
                float la = -8.0f * log1pf(expf(ap4[q])) * rr;
                av[q] = expf(la);
                bv[q] = sqrtf(-expm1f(2.0f * la)) * ii * xcv[q];
            }
            __half2* da = (__half2*)(out0h + row * N + gcol + j * 4);
            da[0] = __floats2half2_rn(av[0], av[1]);
            da[1] = __floats2half2_rn(av[2], av[3]);
            __half2* db = (__half2*)(out1h + row * N + gcol + j * 4);
            db[0] = __floats2half2_rn(bv[0], bv[1]);
            db[1] = __floats2half2_rn(bv[2], bv[3]);
        }
    }
}

// ============================================================================
// fp32->fp16 weight conversion: 4 segments per launch, 16B stores.
// ============================================================================
struct F2HSeg { const float* src; __half* dst; size_t n8; };  // n8 = n/8
struct F2HArgs4 { F2HSeg seg[4]; };

__global__ void f2h4_kernel(F2HArgs4 args) {
    #pragma unroll
    for (int s = 0; s < 4; s++) {
        const float4* src = (const float4*)args.seg[s].src;
        uint4* dst = (uint4*)args.seg[s].dst;
        size_t n8 = args.seg[s].n8;
        for (size_t i = (size_t)blockIdx.x * blockDim.x + threadIdx.x; i < n8;
             i += (size_t)gridDim.x * blockDim.x) {
            float4 v0 = src[2 * i];
            float4 v1 = src[2 * i + 1];
            __half2 h0 = __floats2half2_rn(v0.x, v0.y);
            __half2 h1 = __floats2half2_rn(v0.z, v0.w);
            __half2 h2 = __floats2half2_rn(v1.x, v1.y);
            __half2 h3 = __floats2half2_rn(v1.z, v1.w);
            uint4 u;
            u.x = *reinterpret_cast<unsigned*>(&h0);
            u.y = *reinterpret_cast<unsigned*>(&h1);
            u.z = *reinterpret_cast<unsigned*>(&h2);
            u.w = *reinterpret_cast<unsigned*>(&h3);
            dst[i] = u;
        }
    }
}

// ============================================================================
// RMSNorm: fp32 in, fp16 out (row = 2048, 256 threads x 8 elems).
// ============================================================================
__global__ void rmsnorm_h_kernel(const float* __restrict__ x,
                                 const float* __restrict__ w,
                                 __half* __restrict__ out) {
    const int D = D_DIM;
    const float* row = x + (size_t)blockIdx.x * D;
    __half* orow = out + (size_t)blockIdx.x * D;
    const int tid = threadIdx.x;

    float4 v0 = *(const float4*)(row + tid * 8);
    float4 v1 = *(const float4*)(row + tid * 8 + 4);
    float s = v0.x * v0.x + v0.y * v0.y + v0.z * v0.z + v0.w * v0.w
            + v1.x * v1.x + v1.y * v1.y + v1.z * v1.z + v1.w * v1.w;
    #pragma unroll
    for (int off = 16; off > 0; off >>= 1)
        s += __shfl_xor_sync(0xFFFFFFFF, s, off);
    __shared__ float red[8];
    int lane = tid & 31, warp = tid >> 5;
    if (lane == 0) red[warp] = s;
    __syncthreads();
    if (warp == 0) {
        float t = (lane < 8) ? red[lane] : 0.0f;
        #pragma unroll
        for (int off = 4; off > 0; off >>= 1)
            t += __shfl_xor_sync(0xFFFFFFFF, t, off);
        if (lane == 0) red[0] = t;
    }
    __syncthreads();
    float inv = rsqrtf(red[0] / (float)D + 1e-8f);

    float4 w0 = *(const float4*)(w + tid * 8);
    float4 w1 = *(const float4*)(w + tid * 8 + 4);
    __half2* o = (__half2*)(orow + tid * 8);
    o[0] = __floats2half2_rn(w0.x * v0.x * inv, w0.y * v0.y * inv);
    o[1] = __floats2half2_rn(w0.z * v0.z * inv, w0.w * v0.w * inv);
    o[2] = __floats2half2_rn(w1.x * v1.x * inv, w1.y * v1.y * inv);
    o[3] = __floats2half2_rn(w1.z * v1.z * inv, w1.w * v1.w * inv);
}

// RMSNorm: fp16 in, fp16 out (fp32 math).
__global__ void rmsnorm_hh_kernel(const __half* __restrict__ x,
                                  const float* __restrict__ w,
                                  __half* __restrict__ out) {
    const int D = D_DIM;
    const __half2* row2 = (const __half2*)(x + (size_t)blockIdx.x * D);
    __half* orow = out + (size_t)blockIdx.x * D;
    const int tid = threadIdx.x;

    float2 xv[4];
    #pragma unroll
    for (int q = 0; q < 4; q++)
        xv[q] = __half22float2(row2[tid * 4 + q]);
    float s = 0.0f;
    #pragma unroll
    for (int q = 0; q < 4; q++)
        s += xv[q].x * xv[q].x + xv[q].y * xv[q].y;
    #pragma unroll
    for (int off = 16; off > 0; off >>= 1)
        s += __shfl_xor_sync(0xFFFFFFFF, s, off);
    __shared__ float red[8];
    int lane = tid & 31, warp = tid >> 5;
    if (lane == 0) red[warp] = s;
    __syncthreads();
    if (warp == 0) {
        float t = (lane < 8) ? red[lane] : 0.0f;
        #pragma unroll
        for (int off = 4; off > 0; off >>= 1)
            t += __shfl_xor_sync(0xFFFFFFFF, t, off);
        if (lane == 0) red[0] = t;
    }
    __syncthreads();
    float inv = rsqrtf(red[0] / (float)D + 1e-8f);

    float4 w0 = *(const float4*)(w + tid * 8);
    float4 w1 = *(const float4*)(w + tid * 8 + 4);
    __half2* o = (__half2*)(orow + tid * 8);
    o[0] = __floats2half2_rn(w0.x * xv[0].x * inv, w0.y * xv[0].y * inv);
    o[1] = __floats2half2_rn(w0.z * xv[1].x * inv, w0.w * xv[1].y * inv);
    o[2] = __floats2half2_rn(w1.x * xv[2].x * inv, w1.y * xv[2].y * inv);
    o[3] = __floats2half2_rn(w1.z * xv[3].x * inv, w1.w * xv[3].y * inv);
}

// ============================================================================
// Causal depthwise conv (K=4): fp16 in/out, 2 tokens x 8 channels per thread.
// ============================================================================
__global__ void conv_h_kernel(const __half* __restrict__ xh,
                              const float* __restrict__ w,
                              const float* __restrict__ bias,
                              __half* __restrict__ yh) {
    const int i = blockIdx.x * blockDim.x + threadIdx.x;  // TOKENS*H/16 thr
    const int h8 = (i & (H_DIM / 8 - 1)) * 8;
    const int tp = i >> 8;            // token-pair index
    const int tok0 = tp * 2;
    const int t = tok0 & (S_LEN - 1); // even; pair never crosses batch
    const int bb = tok0 >> 11;

    float wv[4][8];
    #pragma unroll
    for (int k = 0; k < KCONV; k++) {
        float4 a = *(const float4*)(w + k * H_DIM + h8);
        float4 b = *(const float4*)(w + k * H_DIM + h8 + 4);
        wv[k][0] = a.x; wv[k][1] = a.y; wv[k][2] = a.z; wv[k][3] = a.w;
        wv[k][4] = b.x; wv[k][5] = b.y; wv[k][6] = b.z; wv[k][7] = b.w;
    }
    float acc0[8], acc1[8];
    {
        float4 b0 = *(const float4*)(bias + h8);
        float4 b1 = *(const float4*)(bias + h8 + 4);
        acc0[0] = b0.x; acc0[1] = b0.y; acc0[2] = b0.z; acc0[3] = b0.w;
        acc0[4] = b1.x; acc0[5] = b1.y; acc0[6] = b1.z; acc0[7] = b1.w;
        #pragma unroll
        for (int q = 0; q < 8; q++) acc1[q] = acc0[q];
    }

    #pragma unroll
    for (int rr = -3; rr <= 1; rr++) {
        int tt = t + rr;
        if (tt < 0) continue;
        const __half2* xr = (const __half2*)(
            xh + ((size_t)(bb * S_LEN + tt)) * H_DIM + h8);
        float2 x0 = __half22float2(xr[0]);
        float2 x1 = __half22float2(xr[1]);
        float2 x2 = __half22float2(xr[2]);
        float2 x3 = __half22float2(xr[3]);
        float xv[8] = { x0.x, x0.y, x1.x, x1.y, x2.x, x2.y, x3.x, x3.y };
        int k0 = rr + 3;
        int k1 = rr + 2;
        if (k0 <= 3) {
            #pragma unroll
            for (int q = 0; q < 8; q++)
                acc0[q] = fmaf(wv[k0][q], xv[q], acc0[q]);
        }
        if (k1 >= 0) {
            #pragma unroll
            for (int q = 0; q < 8; q++)
                acc1[q] = fmaf(wv[k1][q], xv[q], acc1[q]);
        }
    }
    __half2* o0 = (__half2*)(yh + (size_t)(bb * S_LEN + t) * H_DIM + h8);
    o0[0] = __floats2half2_rn(acc0[0], acc0[1]);
    o0[1] = __floats2half2_rn(acc0[2], acc0[3]);
    o0[2] = __floats2half2_rn(acc0[4], acc0[5]);
    o0[3] = __floats2half2_rn(acc0[6], acc0[7]);
    __half2* o1 = (__half2*)(yh + (size_t)(bb * S_LEN + t + 1) * H_DIM + h8);
    o1[0] = __floats2half2_rn(acc1[0], acc1[1]);
    o1[1] = __floats2half2_rn(acc1[2], acc1[3]);
    o1[2] = __floats2half2_rn(acc1[4], acc1[5]);
    o1[3] = __floats2half2_rn(acc1[6], acc1[7]);
}

// ============================================================================
// Chunked RG-LRU scan, fp16 a/b/left, fp32 state. NCH=32 chunks of 64.
// ============================================================================
__global__ void scan_phaseA(const __half* __restrict__ a,
                            const __half* __restrict__ b,
                            float* __restrict__ Asum,
                            float* __restrict__ Bsum) {
    int idx2 = blockIdx.x * blockDim.x + threadIdx.x;   // BNH/2 threads
    int h2 = idx2 & (H_DIM / 2 - 1);
    int c = (idx2 >> 10) & (NCH - 1);
    int bb = idx2 >> 15;
    size_t base2 = (((size_t)(bb * S_LEN + c * CHL)) * H_DIM) / 2 + h2;
    const __half2* a2 = (const __half2*)a;
    const __half2* b2 = (const __half2*)b;
    float2 A = make_float2(1.0f, 1.0f), B = make_float2(0.0f, 0.0f);
    #pragma unroll 4
    for (int t = 0; t < CHL; t++) {
        size_t o = base2 + (size_t)t * (H_DIM / 2);
        float2 av = __half22float2(a2[o]);
        float2 bv = __half22float2(b2[o]);
        B.x = fmaf(av.x, B.x, bv.x);
        B.y = fmaf(av.y, B.y, bv.y);
        A.x *= av.x;
        A.y *= av.y;
    }
    size_t s2 = ((size_t)(bb * NCH + c) * H_DIM) / 2 + h2;
    ((float2*)Asum)[s2] = A;
    ((float2*)Bsum)[s2] = B;
}

__global__ void scan_phaseB(const float* __restrict__ Asum,
                            const float* __restrict__ Bsum,
                            float* __restrict__ init) {
    int idx = blockIdx.x * blockDim.x + threadIdx.x;    // B*H/2 threads
    int h2 = idx & (H_DIM / 2 - 1);
    int bb = idx >> 10;
    float2 state = make_float2(0.0f, 0.0f);
    #pragma unroll
    for (int c = 0; c < NCH; c++) {
        size_t s2 = ((size_t)(bb * NCH + c) * H_DIM) / 2 + h2;
        ((float2*)init)[s2] = state;
        float2 A = ((const float2*)Asum)[s2];
        float2 B = ((const float2*)Bsum)[s2];
        state.x = fmaf(A.x, state.x, B.x);
        state.y = fmaf(A.y, state.y, B.y);
    }
}

__global__ void scan_phaseC(const __half* __restrict__ a,
                            const __half* __restrict__ b,
                            const float* __restrict__ init,
                            const __half* __restrict__ left,
                            __half* __restrict__ lh) {
    int idx2 = blockIdx.x * blockDim.x + threadIdx.x;   // BNH/2 threads
    int h2 = idx2 & (H_DIM / 2 - 1);
    int c = (idx2 >> 10) & (NCH - 1);
    int bb = idx2 >> 15;
    size_t base2 = (((size_t)(bb * S_LEN + c * CHL)) * H_DIM) / 2 + h2;
    size_t s2 = ((size_t)(bb * NCH + c) * H_DIM) / 2 + h2;
    const __half2* a2 = (const __half2*)a;
    const __half2* b2 = (const __half2*)b;
    const __half2* l2 = (const __half2*)left;
    __half2* o2 = (__half2*)lh;
    float2 state = ((const float2*)init)[s2];
    #pragma unroll 4
    for (int t = 0; t < CHL; t++) {
        size_t o = base2 + (size_t)t * (H_DIM / 2);
        float2 av = __half22float2(a2[o]);
        float2 bv = __half22float2(b2[o]);
        float2 lv = __half22float2(l2[o]);
        state.x = fmaf(av.x, state.x, bv.x);
        state.y = fmaf(av.y, state.y, bv.y);
        o2[o] = __floats2half2_rn(lv.x * state.x, lv.y * state.y);
    }
}

// ============================================================================
// Host launch
// ============================================================================
template <int ACT0, int ACT1, bool RES, bool OUTH, bool RESH>
static inline void launch_gemm(const __half* A,
                               const __half* B0, const __half* B1,
                               void* C0, int ldc0, const float* bias0,
                               void* C1, int ldc1, const float* bias1,
                               const void* res,
                               int M, int Ntot, int K, int Nsplit,
                               int ldb0, int ldb1) {
    dim3 grid(Ntot / BN, M / BM);
    gemm_h_kernel<ACT0, ACT1, RES, OUTH, RESH><<<grid, 256, GEMM_SMEM>>>(
        A, B0, B1, C0, ldc0, bias0, C1, ldc1, bias1, res,
        M, K, Nsplit, ldb0, ldb1);
}

extern "C" void kernel_launch(void* const* d_in, const int* in_sizes, int n_in,
                              void* d_out, int out_size) {
    (void)in_sizes; (void)n_in; (void)out_size;
    const float* x       = (const float*)d_in[0];
    const float* norm1_w = (const float*)d_in[1];
    const float* left_W  = (const float*)d_in[2];
    const float* left_b  = (const float*)d_in[3];
    const float* right_W = (const float*)d_in[4];
    const float* right_b = (const float*)d_in[5];
    const float* conv_w  = (const float*)d_in[6];
    const float* conv_b  = (const float*)d_in[7];
    const float* ga_W    = (const float*)d_in[8];
    const float* ga_b    = (const float*)d_in[9];
    const float* gx_W    = (const float*)d_in[10];
    const float* gx_b    = (const float*)d_in[11];
    const float* a_param = (const float*)d_in[12];
    const float* out_W   = (const float*)d_in[13];
    const float* out_b   = (const float*)d_in[14];
    const float* norm2_w = (const float*)d_in[15];
    const float* up1_W   = (const float*)d_in[16];
    const float* up1_b   = (const float*)d_in[17];
    const float* up2_W   = (const float*)d_in[18];
    const float* up2_b   = (const float*)d_in[19];
    const float* down_W  = (const float*)d_in[20];
    const float* down_b  = (const float*)d_in[21];
    float* out = (float*)d_out;

    cudaFuncSetAttribute(gemm_h_kernel<1, 0, false, true, false>,
                         cudaFuncAttributeMaxDynamicSharedMemorySize, GEMM_SMEM);
    cudaFuncSetAttribute(gemm_h_kernel<0, 0, true, true, false>,
                         cudaFuncAttributeMaxDynamicSharedMemorySize, GEMM_SMEM);
    cudaFuncSetAttribute(gemm_h_kernel<0, 0, true, false, true>,
                         cudaFuncAttributeMaxDynamicSharedMemorySize, GEMM_SMEM);
    cudaFuncSetAttribute(gemm_dual_kernel<0>,
                         cudaFuncAttributeMaxDynamicSharedMemorySize, GEMM_D_SMEM);
    cudaFuncSetAttribute(gemm_dual_kernel<1>,
                         cudaFuncAttributeMaxDynamicSharedMemorySize, GEMM_D_SMEM);

    float* scratch = nullptr;
    cudaGetSymbolAddress((void**)&scratch, g_scratch);
    float* Asum = scratch;                       // [BNH]
    float* Bsum = Asum + BNH;
    float* init = Bsum + BNH;
    __half* xnh   = (__half*)(init + BNH);       // [TOKENS, D]
    __half* rph   = xnh + TD;                    // [TOKENS, H]
    __half* cvh   = rph + TD;                    // [TOKENS, H]
    __half* lefth = cvh + TD;                    // [TOKENS, H]
    __half* abh   = lefth + TD;                  // [TOKENS, H]
    __half* bbh   = abh + TD;                    // [TOKENS, H]
    __half* lhh   = bbh + TD;                    // [TOKENS, H]
    __half* x1h   = lhh + TD;                    // [TOKENS, D]
    __half* x1nh  = x1h + TD;                    // [TOKENS, D]
    __half* f1gh  = x1nh + TD;                   // [TOKENS, F]
    __half* wh    = f1gh + TF;
    __half* leftWh  = wh;
    __half* rightWh = leftWh  + (size_t)D_DIM * H_DIM;
    __half* gaWh    = rightWh + (size_t)D_DIM * H_DIM;
    __half* gxWh    = gaWh    + (size_t)H_DIM * H_DIM;
    __half* outWh   = gxWh    + (size_t)H_DIM * H_DIM;
    __half* up1Wh   = outWh   + (size_t)H_DIM * D_DIM;
    __half* up2Wh   = up1Wh   + (size_t)D_DIM * F_DIM;
    __half* downWh  = up2Wh   + (size_t)D_DIM * F_DIM;

    // Side stream for overlap (created per call; capture-legal, no device mem).
    cudaStream_t s2;
    cudaStreamCreateWithFlags(&s2, cudaStreamNonBlocking);
    cudaEvent_t evFork, evNorm, evWts;
    cudaEventCreateWithFlags(&evFork, cudaEventDisableTiming);
    cudaEventCreateWithFlags(&evNorm, cudaEventDisableTiming);
    cudaEventCreateWithFlags(&evWts, cudaEventDisableTiming);

    // fork s2 off the main stream
    cudaEventRecord(evFork, 0);
    cudaStreamWaitEvent(s2, evFork, 0);

    // s2: rmsnorm1 (needs only x), then weight conversion part2
    rmsnorm_h_kernel<<<TOKENS, 256, 0, s2>>>(x, norm1_w, xnh);
    cudaEventRecord(evNorm, s2);
    {
        F2HArgs4 fa;
        fa.seg[0] = { out_W,  outWh,  (size_t)H_DIM * D_DIM / 8 };
        fa.seg[1] = { up1_W,  up1Wh,  (size_t)D_DIM * F_DIM / 8 };
        fa.seg[2] = { up2_W,  up2Wh,  (size_t)D_DIM * F_DIM / 8 };
        fa.seg[3] = { down_W, downWh, (size_t)F_DIM * D_DIM / 8 };
        f2h4_kernel<<<1184, 256, 0, s2>>>(fa);
    }
    cudaEventRecord(evWts, s2);

    // main: weight conversion part1 (LR + gates)
    {
        F2HArgs4 fa;
        fa.seg[0] = { left_W,  leftWh,  (size_t)D_DIM * H_DIM / 8 };
        fa.seg[1] = { right_W, rightWh, (size_t)D_DIM * H_DIM / 8 };
        fa.seg[2] = { ga_W,    gaWh,    (size_t)H_DIM * H_DIM / 8 };
        fa.seg[3] = { gx_W,    gxWh,    (size_t)H_DIM * H_DIM / 8 };
        f2h4_kernel<<<1184, 256>>>(fa);
    }
    cudaStreamWaitEvent(0, evNorm, 0);

    // ---- recurrent sub-block (main stream) ----
    launch_gemm<1, 0, false, true, false>(
        xnh, leftWh, rightWh,
        lefth, H_DIM, left_b, rph, H_DIM, right_b, nullptr,
        TOKENS, 2 * H_DIM, D_DIM, H_DIM, H_DIM, H_DIM);

    conv_h_kernel<<<TOKENS * H_DIM / 16 / 256, 256>>>(rph, conv_w, conv_b, cvh);

    {
        dim3 grid(H_DIM / BND, TOKENS / BM);
        gemm_dual_kernel<1><<<grid, 256, GEMM_D_SMEM>>>(
            cvh, gaWh, gxWh, abh, bbh, ga_b, gx_b,
            cvh, a_param, TOKENS, H_DIM, H_DIM, H_DIM);
    }

    {
        const int tA2 = (int)(BNH / 2);           // 65536
        scan_phaseA<<<tA2 / 256, 256>>>(abh, bbh, Asum, Bsum);
        scan_phaseB<<<(B_SZ * H_DIM / 2) / 256, 256>>>(Asum, Bsum, init);
        scan_phaseC<<<tA2 / 256, 256>>>(abh, bbh, init, lefth, lhh);
    }

    // join: remaining weights must be converted before out-GEMM
    cudaStreamWaitEvent(0, evWts, 0);

    launch_gemm<0, 0, true, true, false>(
        lhh, outWh, outWh,
        x1h, D_DIM, out_b, nullptr, 0, nullptr, x,
        TOKENS, D_DIM, H_DIM, D_DIM, D_DIM, D_DIM);

    // ---- gated MLP sub-block ----
    rmsnorm_hh_kernel<<<TOKENS, 256>>>(x1h, norm2_w, x1nh);

    {
        dim3 grid(F_DIM / BND, TOKENS / BM);
        gemm_dual_kernel<0><<<grid, 256, GEMM_D_SMEM>>>(
            x1nh, up1Wh, up2Wh, f1gh, nullptr, up1_b, up2_b,
            nullptr, nullptr, TOKENS, F_DIM, D_DIM, F_DIM);
    }

    launch_gemm<0, 0, true, false, true>(
        f1gh, downWh, downWh,
        out, D_DIM, down_b, nullptr, 0, nullptr, x1h,
        TOKENS, D_DIM, F_DIM, D_DIM, D_DIM, D_DIM);
}